// round 4
// baseline (speedup 1.0000x reference)
#include <cuda_runtime.h>
#include <cuda_bf16.h>
#include <cstdint>

#define T_TOK 8192
#define HDIM  1024
#define NEXP  8
#define TPAD  (T_TOK + NEXP*128)

#define BM 128
#define BN 256
#define BK 64
#define NITER 48        // 3072 / 64

// ---------------- device scratch ----------------
__device__ int   g_counts[NEXP];
__device__ int   g_offpad[NEXP + 1];
__device__ int   g_cursor[NEXP];
__device__ int   g_expert[T_TOK];
__device__ float g_gate[T_TOK];
__device__ int   g_tokpad[TPAD];
__device__ __nv_bfloat16 g_xhi[(size_t)T_TOK * HDIM];   // token order (GEMM gathers)
__device__ __nv_bfloat16 g_xlo[(size_t)T_TOK * HDIM];
__device__ __nv_bfloat16 g_whi[(size_t)NEXP * HDIM * HDIM];  // [e][n][k]
__device__ __nv_bfloat16 g_wlo[(size_t)NEXP * HDIM * HDIM];

// ---------------- helpers ----------------
__device__ __forceinline__ uint32_t smem_u32(const void* p) {
    uint32_t a;
    asm("{ .reg .u64 t; cvta.to.shared.u64 t, %1; cvt.u32.u64 %0, t; }" : "=r"(a) : "l"(p));
    return a;
}
__device__ __forceinline__ void cp16(uint32_t dst, const void* src) {
    asm volatile("cp.async.cg.shared.global [%0], [%1], 16;" :: "r"(dst), "l"(src));
}
__device__ __forceinline__ void cp_commit() {
    asm volatile("cp.async.commit_group;" ::: "memory");
}
template <int N>
__device__ __forceinline__ void cp_wait() {
    asm volatile("cp.async.wait_group %0;" :: "n"(N) : "memory");
}
#define LDSM4(R, addr) \
    asm volatile("ldmatrix.sync.aligned.m8n8.x4.shared.b16 {%0,%1,%2,%3}, [%4];" \
                 : "=r"((R)[0]), "=r"((R)[1]), "=r"((R)[2]), "=r"((R)[3]) : "r"(addr))
#define MMA16816(D, A, B0, B1) \
    asm volatile("mma.sync.aligned.m16n8k16.row.col.f32.bf16.bf16.f32 " \
                 "{%0,%1,%2,%3}, {%4,%5,%6,%7}, {%8,%9}, {%0,%1,%2,%3};" \
                 : "+f"((D)[0]), "+f"((D)[1]), "+f"((D)[2]), "+f"((D)[3]) \
                 : "r"((A)[0]), "r"((A)[1]), "r"((A)[2]), "r"((A)[3]), "r"(B0), "r"(B1))

// ---------------- phase 1: router (no atomics) ----------------
__global__ void router_kernel(const float* __restrict__ x,
                              const float* __restrict__ rw,
                              const float* __restrict__ rb) {
    int gwarp = (blockIdx.x * blockDim.x + threadIdx.x) >> 5;
    int lane  = threadIdx.x & 31;
    if (gwarp >= T_TOK) return;

    const float* xr = x + (size_t)gwarp * HDIM;
    float acc[NEXP];
#pragma unroll
    for (int e = 0; e < NEXP; e++) acc[e] = 0.f;

#pragma unroll
    for (int i = 0; i < HDIM / 128; i++) {
        int h = (i * 32 + lane) * 4;
        float4 xv = *reinterpret_cast<const float4*>(xr + h);
        float xa[4] = {xv.x, xv.y, xv.z, xv.w};
#pragma unroll
        for (int c = 0; c < 4; c++) {
            const float4 w0 = __ldg(reinterpret_cast<const float4*>(rw + (size_t)(h + c) * NEXP));
            const float4 w1 = __ldg(reinterpret_cast<const float4*>(rw + (size_t)(h + c) * NEXP + 4));
            float xc = xa[c];
            acc[0] += xc * w0.x; acc[1] += xc * w0.y;
            acc[2] += xc * w0.z; acc[3] += xc * w0.w;
            acc[4] += xc * w1.x; acc[5] += xc * w1.y;
            acc[6] += xc * w1.z; acc[7] += xc * w1.w;
        }
    }
#pragma unroll
    for (int e = 0; e < NEXP; e++) {
#pragma unroll
        for (int off = 16; off > 0; off >>= 1)
            acc[e] += __shfl_xor_sync(0xffffffffu, acc[e], off);
    }
    if (lane == 0) {
        float logit[NEXP];
        float best = -1e30f;
        int   bi = 0;
#pragma unroll
        for (int e = 0; e < NEXP; e++) {
            logit[e] = acc[e] + rb[e];
            if (logit[e] > best) { best = logit[e]; bi = e; }
        }
        float s = 0.f;
#pragma unroll
        for (int e = 0; e < NEXP; e++) s += expf(logit[e] - best);
        g_expert[gwarp] = bi;
        g_gate[gwarp]   = 1.0f / s;
    }
}

// ---------------- phase 2: counts + padded scan (one block) ----------------
__global__ void scan_kernel() {
    __shared__ int cnt[NEXP];
    int tid = threadIdx.x;
    if (tid < NEXP) cnt[tid] = 0;
    __syncthreads();
    int local[NEXP];
#pragma unroll
    for (int e = 0; e < NEXP; e++) local[e] = 0;
    for (int t = tid; t < T_TOK; t += blockDim.x) local[g_expert[t]]++;
#pragma unroll
    for (int e = 0; e < NEXP; e++)
        if (local[e]) atomicAdd(&cnt[e], local[e]);
    __syncthreads();
    if (tid == 0) {
        int o = 0;
#pragma unroll
        for (int e = 0; e < NEXP; e++) {
            g_counts[e] = cnt[e];
            g_offpad[e] = o;
            g_cursor[e] = o;
            o += ((cnt[e] + 127) >> 7) << 7;
        }
        g_offpad[NEXP] = o;
    }
}

// ---------------- phase 3: permutation ----------------
__global__ void assign_kernel() {
    int t = blockIdx.x * blockDim.x + threadIdx.x;
    if (t < T_TOK) {
        int e = g_expert[t];
        int slot = atomicAdd(&g_cursor[e], 1);
        g_tokpad[slot] = t;
    }
}

// ---------------- phase 4: split x (coalesced, token order) ----------------
__global__ void split_x_kernel(const float* __restrict__ x) {
    int t    = (blockIdx.x * blockDim.x + threadIdx.x) >> 5;
    int lane = threadIdx.x & 31;
    const float* xr = x + (size_t)t * HDIM;
    __nv_bfloat16* hi = g_xhi + (size_t)t * HDIM;
    __nv_bfloat16* lo = g_xlo + (size_t)t * HDIM;
#pragma unroll
    for (int i = 0; i < 4; i++) {
        int base = (i * 32 + lane) * 8;
        float4 a = *reinterpret_cast<const float4*>(xr + base);
        float4 b = *reinterpret_cast<const float4*>(xr + base + 4);
        float va[8] = {a.x, a.y, a.z, a.w, b.x, b.y, b.z, b.w};
        uint32_t hw[4], lw[4];
#pragma unroll
        for (int q = 0; q < 4; q++) {
            __nv_bfloat16 h0 = __float2bfloat16_rn(va[2*q]);
            __nv_bfloat16 h1 = __float2bfloat16_rn(va[2*q+1]);
            __nv_bfloat16 l0 = __float2bfloat16_rn(va[2*q]   - __bfloat162float(h0));
            __nv_bfloat16 l1 = __float2bfloat16_rn(va[2*q+1] - __bfloat162float(h1));
            hw[q] = (uint32_t)__bfloat16_as_ushort(h0) | ((uint32_t)__bfloat16_as_ushort(h1) << 16);
            lw[q] = (uint32_t)__bfloat16_as_ushort(l0) | ((uint32_t)__bfloat16_as_ushort(l1) << 16);
        }
        *reinterpret_cast<uint4*>(hi + base) = make_uint4(hw[0], hw[1], hw[2], hw[3]);
        *reinterpret_cast<uint4*>(lo + base) = make_uint4(lw[0], lw[1], lw[2], lw[3]);
    }
}

// ---------------- phase 5: transpose + split W (packed writes) ----------------
// tile: 64 (k) x 32 (n); write bf16x2 packed -> 128B per warp store
__global__ void split_w_kernel(const float* __restrict__ ew) {
    __shared__ float tile[64][33];
    int e  = blockIdx.z;
    int k0 = blockIdx.y * 64, n0 = blockIdx.x * 32;
    int tx = threadIdx.x, ty = threadIdx.y;   // 32 x 8
    const float* W = ew + (size_t)e * HDIM * HDIM;
#pragma unroll
    for (int p = 0; p < 8; p++)
        tile[ty + p * 8][tx] = W[(size_t)(k0 + ty + p * 8) * HDIM + n0 + tx];
    __syncthreads();
    int tid = ty * 32 + tx;
    int l   = tid & 31;        // k-pair index: k = 2*l
    int nr  = tid >> 5;        // 0..7
    uint32_t* whi32 = reinterpret_cast<uint32_t*>(g_whi);
    uint32_t* wlo32 = reinterpret_cast<uint32_t*>(g_wlo);
#pragma unroll
    for (int q = 0; q < 4; q++) {
        int n = nr + q * 8;
        float v0 = tile[2 * l][n], v1 = tile[2 * l + 1][n];
        __nv_bfloat16 h0 = __float2bfloat16_rn(v0);
        __nv_bfloat16 h1 = __float2bfloat16_rn(v1);
        __nv_bfloat16 l0 = __float2bfloat16_rn(v0 - __bfloat162float(h0));
        __nv_bfloat16 l1 = __float2bfloat16_rn(v1 - __bfloat162float(h1));
        size_t idx = ((size_t)e * HDIM + (n0 + n)) * (HDIM / 2) + (k0 / 2 + l);
        whi32[idx] = (uint32_t)__bfloat16_as_ushort(h0) | ((uint32_t)__bfloat16_as_ushort(h1) << 16);
        wlo32[idx] = (uint32_t)__bfloat16_as_ushort(l0) | ((uint32_t)__bfloat16_as_ushort(l1) << 16);
    }
}

// ---------------- phase 6: grouped bf16 HMMA GEMM (128x256) ----------------
// SMEM: As 2x16KB @0, Bs 2x32KB @32768, tok @98304, gate @98816
static constexpr uint32_t OFF_B    = 32768;
static constexpr uint32_t OFF_TOK  = 98304;
static constexpr uint32_t OFF_GATE = 98816;
static constexpr uint32_t SMEM_TOTAL = 99328;

__device__ __forceinline__ void issue_stage(int j, int tid, const int* sTok, int n0,
                                            size_t ebase, uint32_t sbase) {
    int seg = j >> 4;                 // 0: hi*Whi, 1: hi*Wlo, 2: lo*Whi
    int kin = (j & 15) * BK;
    const __nv_bfloat16* Ab = (seg == 2) ? g_xlo : g_xhi;
    const __nv_bfloat16* Bb = ((seg == 1) ? g_wlo : g_whi) + ebase;
    uint32_t as = sbase + (uint32_t)(j & 1) * 16384;
    uint32_t bs = sbase + OFF_B + (uint32_t)(j & 1) * 32768;
#pragma unroll
    for (int i = 0; i < 2; i++) {           // A: 128 rows x 8 chunks, gathered
        int op = tid + i * 512;
        int r = op >> 3, c = op & 7;
        cp16(as + r * 128 + ((c * 16) ^ ((r & 7) << 4)),
             Ab + (size_t)sTok[r] * HDIM + kin + c * 8);
    }
#pragma unroll
    for (int i = 0; i < 4; i++) {           // B: 256 rows x 8 chunks
        int op = tid + i * 512;
        int r = op >> 3, c = op & 7;
        cp16(bs + r * 128 + ((c * 16) ^ ((r & 7) << 4)),
             Bb + (size_t)(n0 + r) * HDIM + kin + c * 8);
    }
    cp_commit();
}

__global__ __launch_bounds__(512, 1)
void moe_gemm_kernel(const float* __restrict__ eb, float* __restrict__ out) {
    extern __shared__ __align__(1024) char smem[];
    const int m0 = blockIdx.y * BM;
    if (m0 >= g_offpad[NEXP]) return;
    int e = 0;
    while (m0 >= g_offpad[e + 1]) e++;
    const int rows_valid = min(BM, g_offpad[e] + g_counts[e] - m0);
    const int n0 = blockIdx.x * BN;
    const int tid = threadIdx.x;
    const uint32_t sbase = smem_u32(smem);
    const size_t ebase = (size_t)e * HDIM * HDIM;
    int* sTok = (int*)(smem + OFF_TOK);
    float* sGate = (float*)(smem + OFF_GATE);

    if (tid < 128) {
        int tok = g_tokpad[m0 + tid] & (T_TOK - 1);
        sTok[tid] = tok;
        sGate[tid] = g_gate[tok];
    }
    __syncthreads();

    issue_stage(0, tid, sTok, n0, ebase, sbase);
    issue_stage(1, tid, sTok, n0, ebase, sbase);

    const int lane = tid & 31, wid = tid >> 5;
    const int warp_m = (wid >> 2) * 32;
    const int warp_n = (wid & 3) * 64;
    const int idx = lane & 7, grp = lane >> 3;

    const int arow = warp_m + (grp & 1) * 8 + idx;
    const uint32_t axor = (uint32_t)((arow & 7) << 4);
    const uint32_t acsel = (uint32_t)((grp >> 1) * 16);
    const int brow = warp_n + (grp >> 1) * 8 + idx;
    const uint32_t bxor = (uint32_t)((brow & 7) << 4);
    const uint32_t bcsel = (uint32_t)((grp & 1) * 16);

    float acc[2][8][4];
#pragma unroll
    for (int i = 0; i < 2; i++)
#pragma unroll
        for (int j = 0; j < 8; j++)
#pragma unroll
            for (int q = 0; q < 4; q++) acc[i][j][q] = 0.f;

    for (int k = 0; k < NITER; k++) {
        cp_wait<1>();
        __syncthreads();
        uint32_t as = sbase + (uint32_t)(k & 1) * 16384;
        uint32_t bs = sbase + OFF_B + (uint32_t)(k & 1) * 32768;
#pragma unroll
        for (int step = 0; step < 4; step++) {
            uint32_t kc = (uint32_t)(step * 32);
            uint32_t a[2][4], b[4][4];
#pragma unroll
            for (int mt = 0; mt < 2; mt++)
                LDSM4(a[mt], as + (uint32_t)(arow + mt * 16) * 128 + ((kc + acsel) ^ axor));
#pragma unroll
            for (int bt = 0; bt < 4; bt++)
                LDSM4(b[bt], bs + (uint32_t)(brow + bt * 16) * 128 + ((kc + bcsel) ^ bxor));
#pragma unroll
            for (int mt = 0; mt < 2; mt++)
#pragma unroll
                for (int bt = 0; bt < 4; bt++) {
                    MMA16816(acc[mt][2 * bt],     a[mt], b[bt][0], b[bt][1]);
                    MMA16816(acc[mt][2 * bt + 1], a[mt], b[bt][2], b[bt][3]);
                }
        }
        __syncthreads();
        if (k + 2 < NITER) issue_stage(k + 2, tid, sTok, n0, ebase, sbase);
        else cp_commit();
    }

    // epilogue
    const float* ebias = eb + (size_t)e * HDIM + n0;
    const int colq = (lane & 3) * 2;
#pragma unroll
    for (int mt = 0; mt < 2; mt++) {
        int r_lo = warp_m + mt * 16 + (lane >> 2);
        int r_hi = r_lo + 8;
        bool v_lo = r_lo < rows_valid, v_hi = r_hi < rows_valid;
        int   t_lo = sTok[r_lo],  t_hi = sTok[r_hi];
        float g_lo = sGate[r_lo], g_hi = sGate[r_hi];
        float* o_lo = out + (size_t)t_lo * HDIM + n0;
        float* o_hi = out + (size_t)t_hi * HDIM + n0;
#pragma unroll
        for (int nt = 0; nt < 8; nt++) {
            int col = warp_n + nt * 8 + colq;
            float2 bv = *reinterpret_cast<const float2*>(ebias + col);
            if (v_lo) {
                float2 v;
                v.x = g_lo * (acc[mt][nt][0] + bv.x);
                v.y = g_lo * (acc[mt][nt][1] + bv.y);
                *reinterpret_cast<float2*>(o_lo + col) = v;
            }
            if (v_hi) {
                float2 v;
                v.x = g_hi * (acc[mt][nt][2] + bv.x);
                v.y = g_hi * (acc[mt][nt][3] + bv.y);
                *reinterpret_cast<float2*>(o_hi + col) = v;
            }
        }
    }
}

// ---------------- launch ----------------
extern "C" void kernel_launch(void* const* d_in, const int* in_sizes, int n_in,
                              void* d_out, int out_size) {
    const float* x  = (const float*)d_in[0];
    const float* rw = (const float*)d_in[1];
    const float* rb = (const float*)d_in[2];
    const float* ew = (const float*)d_in[3];
    const float* eb = (const float*)d_in[4];
    float* out = (float*)d_out;

    cudaFuncSetAttribute(moe_gemm_kernel,
                         cudaFuncAttributeMaxDynamicSharedMemorySize, SMEM_TOTAL);

    router_kernel<<<T_TOK / 8, 256>>>(x, rw, rb);        // 1
    scan_kernel<<<1, 256>>>();                           // 2
    assign_kernel<<<T_TOK / 256, 256>>>();               // 3
    split_x_kernel<<<T_TOK / 8, 256>>>(x);               // 4
    split_w_kernel<<<dim3(32, 16, 8), dim3(32, 8)>>>(ew);// 5
    moe_gemm_kernel<<<dim3(HDIM / BN, TPAD / BM), 512, SMEM_TOTAL>>>(eb, out); // 6
}

// round 5
// speedup vs baseline: 1.6546x; 1.6546x over previous
#include <cuda_runtime.h>
#include <cuda_fp16.h>
#include <cstdint>

#define T_TOK 8192
#define HDIM  1024
#define NEXP  8
#define TPAD  (T_TOK + NEXP*128)

#define BM 128
#define BN 128
#define BK 64
#define NITER 16        // 1024 / 64

// ---------------- device scratch ----------------
__device__ int   g_counts[NEXP];
__device__ int   g_offpad[NEXP + 1];
__device__ int   g_cursor[NEXP];
__device__ int   g_expert[T_TOK];
__device__ float g_gate[T_TOK];
__device__ int   g_tokpad[TPAD];
__device__ __half g_xh[(size_t)T_TOK * HDIM];               // token order
__device__ __half g_wh[(size_t)NEXP * HDIM * HDIM];         // [e][n][k]

// ---------------- helpers ----------------
__device__ __forceinline__ uint32_t smem_u32(const void* p) {
    uint32_t a;
    asm("{ .reg .u64 t; cvta.to.shared.u64 t, %1; cvt.u32.u64 %0, t; }" : "=r"(a) : "l"(p));
    return a;
}
__device__ __forceinline__ void cp16(uint32_t dst, const void* src) {
    asm volatile("cp.async.cg.shared.global [%0], [%1], 16;" :: "r"(dst), "l"(src));
}
__device__ __forceinline__ void cp_commit() {
    asm volatile("cp.async.commit_group;" ::: "memory");
}
template <int N>
__device__ __forceinline__ void cp_wait() {
    asm volatile("cp.async.wait_group %0;" :: "n"(N) : "memory");
}
#define LDSM4(R, addr) \
    asm volatile("ldmatrix.sync.aligned.m8n8.x4.shared.b16 {%0,%1,%2,%3}, [%4];" \
                 : "=r"((R)[0]), "=r"((R)[1]), "=r"((R)[2]), "=r"((R)[3]) : "r"(addr))
#define MMA16816(D, A, B0, B1) \
    asm volatile("mma.sync.aligned.m16n8k16.row.col.f32.f16.f16.f32 " \
                 "{%0,%1,%2,%3}, {%4,%5,%6,%7}, {%8,%9}, {%0,%1,%2,%3};" \
                 : "+f"((D)[0]), "+f"((D)[1]), "+f"((D)[2]), "+f"((D)[3]) \
                 : "r"((A)[0]), "r"((A)[1]), "r"((A)[2]), "r"((A)[3]), "r"(B0), "r"(B1))

// ---------------- phase 1: router ----------------
__global__ void router_kernel(const float* __restrict__ x,
                              const float* __restrict__ rw,
                              const float* __restrict__ rb) {
    int gwarp = (blockIdx.x * blockDim.x + threadIdx.x) >> 5;
    int lane  = threadIdx.x & 31;
    if (gwarp >= T_TOK) return;

    const float* xr = x + (size_t)gwarp * HDIM;
    float acc[NEXP];
#pragma unroll
    for (int e = 0; e < NEXP; e++) acc[e] = 0.f;

#pragma unroll
    for (int i = 0; i < HDIM / 128; i++) {
        int h = (i * 32 + lane) * 4;
        float4 xv = *reinterpret_cast<const float4*>(xr + h);
        float xa[4] = {xv.x, xv.y, xv.z, xv.w};
#pragma unroll
        for (int c = 0; c < 4; c++) {
            const float4 w0 = __ldg(reinterpret_cast<const float4*>(rw + (size_t)(h + c) * NEXP));
            const float4 w1 = __ldg(reinterpret_cast<const float4*>(rw + (size_t)(h + c) * NEXP + 4));
            float xc = xa[c];
            acc[0] += xc * w0.x; acc[1] += xc * w0.y;
            acc[2] += xc * w0.z; acc[3] += xc * w0.w;
            acc[4] += xc * w1.x; acc[5] += xc * w1.y;
            acc[6] += xc * w1.z; acc[7] += xc * w1.w;
        }
    }
#pragma unroll
    for (int e = 0; e < NEXP; e++) {
#pragma unroll
        for (int off = 16; off > 0; off >>= 1)
            acc[e] += __shfl_xor_sync(0xffffffffu, acc[e], off);
    }
    if (lane == 0) {
        float logit[NEXP];
        float best = -1e30f;
        int   bi = 0;
#pragma unroll
        for (int e = 0; e < NEXP; e++) {
            logit[e] = acc[e] + rb[e];
            if (logit[e] > best) { best = logit[e]; bi = e; }
        }
        float s = 0.f;
#pragma unroll
        for (int e = 0; e < NEXP; e++) s += expf(logit[e] - best);
        g_expert[gwarp] = bi;
        g_gate[gwarp]   = 1.0f / s;
    }
}

// ---------------- phase 2: counts + padded scan ----------------
__global__ void scan_kernel() {
    __shared__ int cnt[NEXP];
    int tid = threadIdx.x;
    if (tid < NEXP) cnt[tid] = 0;
    __syncthreads();
    int local[NEXP];
#pragma unroll
    for (int e = 0; e < NEXP; e++) local[e] = 0;
    for (int t = tid; t < T_TOK; t += blockDim.x) local[g_expert[t]]++;
#pragma unroll
    for (int e = 0; e < NEXP; e++)
        if (local[e]) atomicAdd(&cnt[e], local[e]);
    __syncthreads();
    if (tid == 0) {
        int o = 0;
#pragma unroll
        for (int e = 0; e < NEXP; e++) {
            g_counts[e] = cnt[e];
            g_offpad[e] = o;
            g_cursor[e] = o;
            o += ((cnt[e] + 127) >> 7) << 7;
        }
        g_offpad[NEXP] = o;
    }
}

// ---------------- phase 3: permutation ----------------
__global__ void assign_kernel() {
    int t = blockIdx.x * blockDim.x + threadIdx.x;
    if (t < T_TOK) {
        int e = g_expert[t];
        int slot = atomicAdd(&g_cursor[e], 1);
        g_tokpad[slot] = t;
    }
}

// ---------------- phase 4: convert x -> fp16 (token order) ----------------
__global__ void convert_x_kernel(const float* __restrict__ x) {
    int t    = (blockIdx.x * blockDim.x + threadIdx.x) >> 5;
    int lane = threadIdx.x & 31;
    const float* xr = x + (size_t)t * HDIM;
    __half* hp = g_xh + (size_t)t * HDIM;
#pragma unroll
    for (int i = 0; i < 4; i++) {
        int base = (i * 32 + lane) * 8;
        float4 a = *reinterpret_cast<const float4*>(xr + base);
        float4 b = *reinterpret_cast<const float4*>(xr + base + 4);
        uint32_t w[4];
        w[0] = __half2_raw(__floats2half2_rn(a.x, a.y)).x | ((uint32_t)__half2_raw(__floats2half2_rn(a.x, a.y)).y << 16);
        // simpler: build via __floats2half2_rn reinterpret
        __half2 h0 = __floats2half2_rn(a.x, a.y);
        __half2 h1 = __floats2half2_rn(a.z, a.w);
        __half2 h2 = __floats2half2_rn(b.x, b.y);
        __half2 h3 = __floats2half2_rn(b.z, b.w);
        w[0] = *reinterpret_cast<uint32_t*>(&h0);
        w[1] = *reinterpret_cast<uint32_t*>(&h1);
        w[2] = *reinterpret_cast<uint32_t*>(&h2);
        w[3] = *reinterpret_cast<uint32_t*>(&h3);
        *reinterpret_cast<uint4*>(hp + base) = make_uint4(w[0], w[1], w[2], w[3]);
    }
}

// ---------------- phase 5: transpose + convert W -> fp16 [e][n][k] ----------
__global__ void convert_w_kernel(const float* __restrict__ ew) {
    __shared__ float tile[64][33];
    int e  = blockIdx.z;
    int k0 = blockIdx.y * 64, n0 = blockIdx.x * 32;
    int tx = threadIdx.x, ty = threadIdx.y;   // 32 x 8
    const float* W = ew + (size_t)e * HDIM * HDIM;
#pragma unroll
    for (int p = 0; p < 8; p++)
        tile[ty + p * 8][tx] = W[(size_t)(k0 + ty + p * 8) * HDIM + n0 + tx];
    __syncthreads();
    int tid = ty * 32 + tx;
    int l   = tid & 31;        // k-pair: k = 2*l
    int nr  = tid >> 5;        // 0..7
    uint32_t* w32 = reinterpret_cast<uint32_t*>(g_wh);
#pragma unroll
    for (int q = 0; q < 4; q++) {
        int n = nr + q * 8;
        __half2 h = __floats2half2_rn(tile[2 * l][n], tile[2 * l + 1][n]);
        size_t idx = ((size_t)e * HDIM + (n0 + n)) * (HDIM / 2) + (k0 / 2 + l);
        w32[idx] = *reinterpret_cast<uint32_t*>(&h);
    }
}

// ---------------- phase 6: grouped fp16 HMMA GEMM (128x128, occ 2) --------
static constexpr uint32_t OFF_B    = 32768;
static constexpr uint32_t OFF_TOK  = 65536;
static constexpr uint32_t OFF_GATE = 66048;
static constexpr uint32_t SMEM_TOTAL = 66560;

__device__ __forceinline__ void issue_stage(int j, int tid, const int* sTok, int n0,
                                            size_t ebase, uint32_t sbase) {
    int kin = j * BK;
    const __half* Bb = g_wh + ebase;
    uint32_t as = sbase + (uint32_t)(j & 1) * 16384;
    uint32_t bs = sbase + OFF_B + (uint32_t)(j & 1) * 16384;
#pragma unroll
    for (int i = 0; i < 4; i++) {           // A: 128 rows x 8 chunks, gathered
        int op = tid + i * 256;
        int r = op >> 3, c = op & 7;
        cp16(as + r * 128 + ((c * 16) ^ ((r & 7) << 4)),
             g_xh + (size_t)sTok[r] * HDIM + kin + c * 8);
    }
#pragma unroll
    for (int i = 0; i < 4; i++) {           // B: 128 rows x 8 chunks
        int op = tid + i * 256;
        int r = op >> 3, c = op & 7;
        cp16(bs + r * 128 + ((c * 16) ^ ((r & 7) << 4)),
             Bb + (size_t)(n0 + r) * HDIM + kin + c * 8);
    }
    cp_commit();
}

__global__ __launch_bounds__(256, 2)
void moe_gemm_kernel(const float* __restrict__ eb, float* __restrict__ out) {
    extern __shared__ __align__(1024) char smem[];
    const int m0 = blockIdx.y * BM;
    if (m0 >= g_offpad[NEXP]) return;
    int e = 0;
    while (m0 >= g_offpad[e + 1]) e++;
    const int rows_valid = min(BM, g_offpad[e] + g_counts[e] - m0);
    const int n0 = blockIdx.x * BN;
    const int tid = threadIdx.x;
    const uint32_t sbase = smem_u32(smem);
    const size_t ebase = (size_t)e * HDIM * HDIM;
    int* sTok = (int*)(smem + OFF_TOK);
    float* sGate = (float*)(smem + OFF_GATE);

    if (tid < 128) {
        int tok = g_tokpad[m0 + tid] & (T_TOK - 1);
        sTok[tid] = tok;
        sGate[tid] = g_gate[tok];
    }
    __syncthreads();

    issue_stage(0, tid, sTok, n0, ebase, sbase);
    issue_stage(1, tid, sTok, n0, ebase, sbase);

    const int lane = tid & 31, wid = tid >> 5;
    const int warp_m = (wid >> 1) * 32;
    const int warp_n = (wid & 1) * 64;
    const int idx = lane & 7, grp = lane >> 3;

    const int arow = warp_m + (grp & 1) * 8 + idx;
    const uint32_t axor = (uint32_t)((arow & 7) << 4);
    const uint32_t acsel = (uint32_t)((grp >> 1) * 16);
    const int brow = warp_n + (grp >> 1) * 8 + idx;
    const uint32_t bxor = (uint32_t)((brow & 7) << 4);
    const uint32_t bcsel = (uint32_t)((grp & 1) * 16);

    float acc[2][8][4];
#pragma unroll
    for (int i = 0; i < 2; i++)
#pragma unroll
        for (int j = 0; j < 8; j++)
#pragma unroll
            for (int q = 0; q < 4; q++) acc[i][j][q] = 0.f;

    for (int k = 0; k < NITER; k++) {
        cp_wait<1>();
        __syncthreads();
        uint32_t as = sbase + (uint32_t)(k & 1) * 16384;
        uint32_t bs = sbase + OFF_B + (uint32_t)(k & 1) * 16384;
#pragma unroll
        for (int step = 0; step < 4; step++) {
            uint32_t kc = (uint32_t)(step * 32);
            uint32_t a[2][4], b[4][4];
#pragma unroll
            for (int mt = 0; mt < 2; mt++)
                LDSM4(a[mt], as + (uint32_t)(arow + mt * 16) * 128 + ((kc + acsel) ^ axor));
#pragma unroll
            for (int bt = 0; bt < 4; bt++)
                LDSM4(b[bt], bs + (uint32_t)(brow + bt * 16) * 128 + ((kc + bcsel) ^ bxor));
#pragma unroll
            for (int mt = 0; mt < 2; mt++)
#pragma unroll
                for (int bt = 0; bt < 4; bt++) {
                    MMA16816(acc[mt][2 * bt],     a[mt], b[bt][0], b[bt][1]);
                    MMA16816(acc[mt][2 * bt + 1], a[mt], b[bt][2], b[bt][3]);
                }
        }
        __syncthreads();
        if (k + 2 < NITER) issue_stage(k + 2, tid, sTok, n0, ebase, sbase);
        else cp_commit();
    }

    // epilogue
    const float* ebias = eb + (size_t)e * HDIM + n0;
    const int colq = (lane & 3) * 2;
#pragma unroll
    for (int mt = 0; mt < 2; mt++) {
        int r_lo = warp_m + mt * 16 + (lane >> 2);
        int r_hi = r_lo + 8;
        bool v_lo = r_lo < rows_valid, v_hi = r_hi < rows_valid;
        int   t_lo = sTok[r_lo],  t_hi = sTok[r_hi];
        float g_lo = sGate[r_lo], g_hi = sGate[r_hi];
        float* o_lo = out + (size_t)t_lo * HDIM + n0;
        float* o_hi = out + (size_t)t_hi * HDIM + n0;
#pragma unroll
        for (int nt = 0; nt < 8; nt++) {
            int col = warp_n + nt * 8 + colq;
            float2 bv = *reinterpret_cast<const float2*>(ebias + col);
            if (v_lo) {
                float2 v;
                v.x = g_lo * (acc[mt][nt][0] + bv.x);
                v.y = g_lo * (acc[mt][nt][1] + bv.y);
                *reinterpret_cast<float2*>(o_lo + col) = v;
            }
            if (v_hi) {
                float2 v;
                v.x = g_hi * (acc[mt][nt][2] + bv.x);
                v.y = g_hi * (acc[mt][nt][3] + bv.y);
                *reinterpret_cast<float2*>(o_hi + col) = v;
            }
        }
    }
}

// ---------------- launch ----------------
extern "C" void kernel_launch(void* const* d_in, const int* in_sizes, int n_in,
                              void* d_out, int out_size) {
    const float* x  = (const float*)d_in[0];
    const float* rw = (const float*)d_in[1];
    const float* rb = (const float*)d_in[2];
    const float* ew = (const float*)d_in[3];
    const float* eb = (const float*)d_in[4];
    float* out = (float*)d_out;

    cudaFuncSetAttribute(moe_gemm_kernel,
                         cudaFuncAttributeMaxDynamicSharedMemorySize, SMEM_TOTAL);

    router_kernel<<<T_TOK / 8, 256>>>(x, rw, rb);          // 1
    scan_kernel<<<1, 256>>>();                             // 2
    assign_kernel<<<T_TOK / 256, 256>>>();                 // 3
    convert_x_kernel<<<T_TOK / 8, 256>>>(x);               // 4
    convert_w_kernel<<<dim3(32, 16, 8), dim3(32, 8)>>>(ew);// 5
    moe_gemm_kernel<<<dim3(HDIM / BN, TPAD / BM), 256, SMEM_TOTAL>>>(eb, out); // 6
}

// round 6
// speedup vs baseline: 1.8417x; 1.1131x over previous
#include <cuda_runtime.h>
#include <cuda_fp16.h>
#include <cstdint>

#define T_TOK 8192
#define HDIM  1024
#define NEXP  8
#define TPAD  (T_TOK + NEXP*128)

#define BM 128
#define BN 128
#define BK 64
#define NITER 16        // 1024 / 64
#define NSTAGE 3

// ---------------- device scratch ----------------
__device__ int   g_counts[NEXP];
__device__ int   g_offpad[NEXP + 1];
__device__ int   g_expert[T_TOK];
__device__ float g_gate[T_TOK];
__device__ int   g_tokpad[TPAD];
__device__ __half g_xh[(size_t)T_TOK * HDIM];               // token order
__device__ __half g_wh[(size_t)NEXP * HDIM * HDIM];         // [e][n][k]

// ---------------- helpers ----------------
__device__ __forceinline__ uint32_t smem_u32(const void* p) {
    uint32_t a;
    asm("{ .reg .u64 t; cvta.to.shared.u64 t, %1; cvt.u32.u64 %0, t; }" : "=r"(a) : "l"(p));
    return a;
}
__device__ __forceinline__ void cp16(uint32_t dst, const void* src) {
    asm volatile("cp.async.cg.shared.global [%0], [%1], 16;" :: "r"(dst), "l"(src));
}
__device__ __forceinline__ void cp_commit() {
    asm volatile("cp.async.commit_group;" ::: "memory");
}
template <int N>
__device__ __forceinline__ void cp_wait() {
    asm volatile("cp.async.wait_group %0;" :: "n"(N) : "memory");
}
#define LDSM4(R, addr) \
    asm volatile("ldmatrix.sync.aligned.m8n8.x4.shared.b16 {%0,%1,%2,%3}, [%4];" \
                 : "=r"((R)[0]), "=r"((R)[1]), "=r"((R)[2]), "=r"((R)[3]) : "r"(addr))
#define MMA16816(D, A, B0, B1) \
    asm volatile("mma.sync.aligned.m16n8k16.row.col.f32.f16.f16.f32 " \
                 "{%0,%1,%2,%3}, {%4,%5,%6,%7}, {%8,%9}, {%0,%1,%2,%3};" \
                 : "+f"((D)[0]), "+f"((D)[1]), "+f"((D)[2]), "+f"((D)[3]) \
                 : "r"((A)[0]), "r"((A)[1]), "r"((A)[2]), "r"((A)[3]), "r"(B0), "r"(B1))

// ---------------- phase 1: transpose + convert W -> fp16 [e][n][k] --------
__global__ void convert_w_kernel(const float* __restrict__ ew) {
    __shared__ float tile[64][33];
    int e  = blockIdx.z;
    int k0 = blockIdx.y * 64, n0 = blockIdx.x * 32;
    int tx = threadIdx.x, ty = threadIdx.y;   // 32 x 8
    const float* W = ew + (size_t)e * HDIM * HDIM;
#pragma unroll
    for (int p = 0; p < 8; p++)
        tile[ty + p * 8][tx] = W[(size_t)(k0 + ty + p * 8) * HDIM + n0 + tx];
    __syncthreads();
    int tid = ty * 32 + tx;
    int l   = tid & 31;        // k-pair: k = 2*l
    int nr  = tid >> 5;        // 0..7
    uint32_t* w32 = reinterpret_cast<uint32_t*>(g_wh);
#pragma unroll
    for (int q = 0; q < 4; q++) {
        int n = nr + q * 8;
        __half2 h = __floats2half2_rn(tile[2 * l][n], tile[2 * l + 1][n]);
        size_t idx = ((size_t)e * HDIM + (n0 + n)) * (HDIM / 2) + (k0 / 2 + l);
        w32[idx] = *reinterpret_cast<uint32_t*>(&h);
    }
}

// ---------------- phase 2: router + convert x -> fp16 ----------------
__global__ void router_kernel(const float* __restrict__ x,
                              const float* __restrict__ rw,
                              const float* __restrict__ rb) {
    int gwarp = (blockIdx.x * blockDim.x + threadIdx.x) >> 5;
    int lane  = threadIdx.x & 31;
    if (gwarp >= T_TOK) return;

    const float* xr = x + (size_t)gwarp * HDIM;
    __half* hp = g_xh + (size_t)gwarp * HDIM;
    float acc[NEXP];
#pragma unroll
    for (int e = 0; e < NEXP; e++) acc[e] = 0.f;

#pragma unroll
    for (int i = 0; i < HDIM / 128; i++) {
        int h = (i * 32 + lane) * 4;
        float4 xv = *reinterpret_cast<const float4*>(xr + h);
        // fused fp16 conversion store (coalesced 8B/lane)
        __half2 c0 = __floats2half2_rn(xv.x, xv.y);
        __half2 c1 = __floats2half2_rn(xv.z, xv.w);
        uint2 pk;
        pk.x = *reinterpret_cast<uint32_t*>(&c0);
        pk.y = *reinterpret_cast<uint32_t*>(&c1);
        *reinterpret_cast<uint2*>(hp + h) = pk;

        float xa[4] = {xv.x, xv.y, xv.z, xv.w};
#pragma unroll
        for (int c = 0; c < 4; c++) {
            const float4 w0 = __ldg(reinterpret_cast<const float4*>(rw + (size_t)(h + c) * NEXP));
            const float4 w1 = __ldg(reinterpret_cast<const float4*>(rw + (size_t)(h + c) * NEXP + 4));
            float xc = xa[c];
            acc[0] += xc * w0.x; acc[1] += xc * w0.y;
            acc[2] += xc * w0.z; acc[3] += xc * w0.w;
            acc[4] += xc * w1.x; acc[5] += xc * w1.y;
            acc[6] += xc * w1.z; acc[7] += xc * w1.w;
        }
    }
#pragma unroll
    for (int e = 0; e < NEXP; e++) {
#pragma unroll
        for (int off = 16; off > 0; off >>= 1)
            acc[e] += __shfl_xor_sync(0xffffffffu, acc[e], off);
    }
    if (lane == 0) {
        float logit[NEXP];
        float best = -1e30f;
        int   bi = 0;
#pragma unroll
        for (int e = 0; e < NEXP; e++) {
            logit[e] = acc[e] + rb[e];
            if (logit[e] > best) { best = logit[e]; bi = e; }
        }
        float s = 0.f;
#pragma unroll
        for (int e = 0; e < NEXP; e++) s += expf(logit[e] - best);
        g_expert[gwarp] = bi;
        g_gate[gwarp]   = 1.0f / s;
    }
}

// ---------------- phase 3: fused counts + scan + permutation --------------
__global__ void scan_assign_kernel() {
    __shared__ int cnt[NEXP];
    __shared__ int cur[NEXP];
    int tid = threadIdx.x;
    if (tid < NEXP) cnt[tid] = 0;
    __syncthreads();
    int local[NEXP];
#pragma unroll
    for (int e = 0; e < NEXP; e++) local[e] = 0;
    for (int t = tid; t < T_TOK; t += blockDim.x) local[g_expert[t]]++;
#pragma unroll
    for (int e = 0; e < NEXP; e++)
        if (local[e]) atomicAdd(&cnt[e], local[e]);
    __syncthreads();
    if (tid == 0) {
        int o = 0;
#pragma unroll
        for (int e = 0; e < NEXP; e++) {
            g_counts[e] = cnt[e];
            g_offpad[e] = o;
            cur[e] = o;
            o += ((cnt[e] + 127) >> 7) << 7;
        }
        g_offpad[NEXP] = o;
    }
    __syncthreads();
    for (int t = tid; t < T_TOK; t += blockDim.x) {
        int e = g_expert[t];
        int slot = atomicAdd(&cur[e], 1);
        g_tokpad[slot] = t;
    }
}

// ---------------- phase 4: grouped fp16 HMMA GEMM (128x128, 3-stage) -------
static constexpr uint32_t OFF_B    = 49152;   // 3 x 16KB A buffers first
static constexpr uint32_t OFF_TOK  = 98304;
static constexpr uint32_t OFF_GATE = 98816;
static constexpr uint32_t SMEM_TOTAL = 99328;

__device__ __forceinline__ void issue_stage(int j, int tid, const int* sTok, int n0,
                                            size_t ebase, uint32_t sbase) {
    int kin = j * BK;
    int buf = j % NSTAGE;
    const __half* Bb = g_wh + ebase;
    uint32_t as = sbase + (uint32_t)buf * 16384;
    uint32_t bs = sbase + OFF_B + (uint32_t)buf * 16384;
#pragma unroll
    for (int i = 0; i < 4; i++) {           // A: 128 rows x 8 chunks, gathered
        int op = tid + i * 256;
        int r = op >> 3, c = op & 7;
        cp16(as + r * 128 + ((c * 16) ^ ((r & 7) << 4)),
             g_xh + (size_t)sTok[r] * HDIM + kin + c * 8);
    }
#pragma unroll
    for (int i = 0; i < 4; i++) {           // B: 128 rows x 8 chunks
        int op = tid + i * 256;
        int r = op >> 3, c = op & 7;
        cp16(bs + r * 128 + ((c * 16) ^ ((r & 7) << 4)),
             Bb + (size_t)(n0 + r) * HDIM + kin + c * 8);
    }
    cp_commit();
}

__global__ __launch_bounds__(256, 2)
void moe_gemm_kernel(const float* __restrict__ eb, float* __restrict__ out) {
    extern __shared__ __align__(1024) char smem[];
    const int m0 = blockIdx.y * BM;
    if (m0 >= g_offpad[NEXP]) return;
    int e = 0;
    while (m0 >= g_offpad[e + 1]) e++;
    const int rows_valid = min(BM, g_offpad[e] + g_counts[e] - m0);
    const int n0 = blockIdx.x * BN;
    const int tid = threadIdx.x;
    const uint32_t sbase = smem_u32(smem);
    const size_t ebase = (size_t)e * HDIM * HDIM;
    int* sTok = (int*)(smem + OFF_TOK);
    float* sGate = (float*)(smem + OFF_GATE);

    if (tid < 128) {
        int tok = g_tokpad[m0 + tid] & (T_TOK - 1);
        sTok[tid] = tok;
        sGate[tid] = g_gate[tok];
    }
    __syncthreads();

    issue_stage(0, tid, sTok, n0, ebase, sbase);
    issue_stage(1, tid, sTok, n0, ebase, sbase);
    issue_stage(2, tid, sTok, n0, ebase, sbase);

    const int lane = tid & 31, wid = tid >> 5;
    const int warp_m = (wid >> 1) * 32;
    const int warp_n = (wid & 1) * 64;
    const int idx = lane & 7, grp = lane >> 3;

    const int arow = warp_m + (grp & 1) * 8 + idx;
    const uint32_t axor = (uint32_t)((arow & 7) << 4);
    const uint32_t acsel = (uint32_t)((grp >> 1) * 16);
    const int brow = warp_n + (grp >> 1) * 8 + idx;
    const uint32_t bxor = (uint32_t)((brow & 7) << 4);
    const uint32_t bcsel = (uint32_t)((grp & 1) * 16);

    float acc[2][8][4];
#pragma unroll
    for (int i = 0; i < 2; i++)
#pragma unroll
        for (int j = 0; j < 8; j++)
#pragma unroll
            for (int q = 0; q < 4; q++) acc[i][j][q] = 0.f;

    for (int k = 0; k < NITER; k++) {
        cp_wait<2>();
        __syncthreads();
        int buf = k % NSTAGE;
        uint32_t as = sbase + (uint32_t)buf * 16384;
        uint32_t bs = sbase + OFF_B + (uint32_t)buf * 16384;
#pragma unroll
        for (int step = 0; step < 4; step++) {
            uint32_t kc = (uint32_t)(step * 32);
            uint32_t a[2][4], b[4][4];
#pragma unroll
            for (int mt = 0; mt < 2; mt++)
                LDSM4(a[mt], as + (uint32_t)(arow + mt * 16) * 128 + ((kc + acsel) ^ axor));
#pragma unroll
            for (int bt = 0; bt < 4; bt++)
                LDSM4(b[bt], bs + (uint32_t)(brow + bt * 16) * 128 + ((kc + bcsel) ^ bxor));
#pragma unroll
            for (int mt = 0; mt < 2; mt++)
#pragma unroll
                for (int bt = 0; bt < 4; bt++) {
                    MMA16816(acc[mt][2 * bt],     a[mt], b[bt][0], b[bt][1]);
                    MMA16816(acc[mt][2 * bt + 1], a[mt], b[bt][2], b[bt][3]);
                }
        }
        __syncthreads();
        if (k + NSTAGE < NITER) issue_stage(k + NSTAGE, tid, sTok, n0, ebase, sbase);
        else cp_commit();
    }

    // epilogue
    const float* ebias = eb + (size_t)e * HDIM + n0;
    const int colq = (lane & 3) * 2;
#pragma unroll
    for (int mt = 0; mt < 2; mt++) {
        int r_lo = warp_m + mt * 16 + (lane >> 2);
        int r_hi = r_lo + 8;
        bool v_lo = r_lo < rows_valid, v_hi = r_hi < rows_valid;
        int   t_lo = sTok[r_lo],  t_hi = sTok[r_hi];
        float g_lo = sGate[r_lo], g_hi = sGate[r_hi];
        float* o_lo = out + (size_t)t_lo * HDIM + n0;
        float* o_hi = out + (size_t)t_hi * HDIM + n0;
#pragma unroll
        for (int nt = 0; nt < 8; nt++) {
            int col = warp_n + nt * 8 + colq;
            float2 bv = *reinterpret_cast<const float2*>(ebias + col);
            if (v_lo) {
                float2 v;
                v.x = g_lo * (acc[mt][nt][0] + bv.x);
                v.y = g_lo * (acc[mt][nt][1] + bv.y);
                *reinterpret_cast<float2*>(o_lo + col) = v;
            }
            if (v_hi) {
                float2 v;
                v.x = g_hi * (acc[mt][nt][2] + bv.x);
                v.y = g_hi * (acc[mt][nt][3] + bv.y);
                *reinterpret_cast<float2*>(o_hi + col) = v;
            }
        }
    }
}

// ---------------- launch ----------------
extern "C" void kernel_launch(void* const* d_in, const int* in_sizes, int n_in,
                              void* d_out, int out_size) {
    const float* x  = (const float*)d_in[0];
    const float* rw = (const float*)d_in[1];
    const float* rb = (const float*)d_in[2];
    const float* ew = (const float*)d_in[3];
    const float* eb = (const float*)d_in[4];
    float* out = (float*)d_out;

    cudaFuncSetAttribute(moe_gemm_kernel,
                         cudaFuncAttributeMaxDynamicSharedMemorySize, SMEM_TOTAL);

    convert_w_kernel<<<dim3(32, 16, 8), dim3(32, 8)>>>(ew);   // 1
    router_kernel<<<T_TOK / 8, 256>>>(x, rw, rb);             // 2
    scan_assign_kernel<<<1, 256>>>();                         // 3
    moe_gemm_kernel<<<dim3(HDIM / BN, TPAD / BM), 256, SMEM_TOTAL>>>(eb, out); // 4
}